// round 1
// baseline (speedup 1.0000x reference)
#include <cuda_runtime.h>
#include <cuda_bf16.h>
#include <math.h>

// ---------------- problem constants ----------------
#define BB 64
#define SS 8
#define TT 8192
#define L1_LEN 8190   // after dil-1 conv
#define L2_LEN 8184   // after dil-3 conv
#define L3_LEN 8166   // after dil-9 conv
#define CEEG 64

// ---------------- device scratch (static, no allocs) ----------------
__device__ float g_x0[(size_t)BB * 8  * TT];   // eeg after 1x1 head
__device__ float g_x1[(size_t)BB * 16 * TT];
__device__ float g_x2[(size_t)BB * 16 * TT];
__device__ float g_x3[(size_t)BB * 16 * TT];   // eeg final features
__device__ float g_nx[BB * 16];                // eeg norms (already sqrt+clamp)
__device__ float g_nst2[BB * SS * 16];         // stim sum-of-squares accumulators
__device__ float g_dot[(size_t)BB * SS * 256]; // dot accumulators

__device__ __forceinline__ float* bufptr(int id) {
    switch (id) {
        case 0: return g_x0;
        case 1: return g_x1;
        case 2: return g_x2;
        default: return g_x3;
    }
}

// ---------------- kernel 1: eeg 1x1 head (64 -> 8), no relu ----------------
__global__ void k_head(const float* __restrict__ eeg,
                       const float* __restrict__ w,      // [8][64]
                       const float* __restrict__ bias)   // [8]
{
    __shared__ float sh_w[512];
    __shared__ float sh_b[8];
    int tid = threadIdx.x;
    for (int i = tid; i < 512; i += 256) sh_w[i] = w[i];
    if (tid < 8) sh_b[tid] = bias[tid];
    __syncthreads();

    size_t idx = (size_t)blockIdx.x * 256 + tid;     // over B*T
    int b = (int)(idx >> 13);
    int t = (int)(idx & (TT - 1));

    const float4* ep = (const float4*)(eeg + idx * 64);
    float acc[8];
#pragma unroll
    for (int c = 0; c < 8; c++) acc[c] = sh_b[c];
#pragma unroll
    for (int q = 0; q < 16; q++) {
        float4 v = ep[q];
#pragma unroll
        for (int c = 0; c < 8; c++) {
            acc[c] += v.x * sh_w[c * 64 + q * 4 + 0]
                    + v.y * sh_w[c * 64 + q * 4 + 1]
                    + v.z * sh_w[c * 64 + q * 4 + 2]
                    + v.w * sh_w[c * 64 + q * 4 + 3];
        }
    }
    float* ob = g_x0 + ((size_t)b * 8) * TT + t;
#pragma unroll
    for (int c = 0; c < 8; c++) ob[(size_t)c * TT] = acc[c];
}

// ---------------- kernel 2: generic dilated conv+relu layer (eeg path) ----------------
template <int CIN, int DIL>
__global__ void k_conv(int inId, int outId,
                       const float* __restrict__ w,     // [16][CIN][3]
                       const float* __restrict__ bias,  // [16]
                       int Lin, int Lout)
{
    const int TILE = 256;
    __shared__ float sh_in[CIN * (TILE + 2 * DIL)];
    __shared__ __align__(16) float sh_w[CIN * 3 * 16];
    __shared__ float sh_b[16];

    const float* in  = bufptr(inId);
    float*       out = bufptr(outId);

    int b   = blockIdx.y;
    int t0  = blockIdx.x * TILE;
    int tid = threadIdx.x;
    int tileOut = min(TILE, Lout - t0);
    if (tileOut <= 0) return;
    int nIn = tileOut + 2 * DIL;

    // weights: w[(co*CIN+ci)*3+k] -> sh_w[(ci*3+k)*16+co]
    for (int i = tid; i < CIN * 48; i += 256) {
        int co = i & 15; int rem = i >> 4; int k = rem % 3; int ci = rem / 3;
        sh_w[i] = w[(co * CIN + ci) * 3 + k];
    }
    if (tid < 16) sh_b[tid] = bias[tid];

    const float* inb = in + ((size_t)b * CIN) * TT;
    for (int i = tid; i < CIN * nIn; i += 256) {
        int ci = i / nIn; int q = i - ci * nIn;
        int t = t0 + q;
        sh_in[ci * (TILE + 2 * DIL) + q] = (t < Lin) ? inb[(size_t)ci * TT + t] : 0.f;
    }
    __syncthreads();

    float* outb = out + ((size_t)b * 16) * TT;
    for (int it = tid; it < 4 * tileOut; it += 256) {
        int cg = it & 3; int p = it >> 2;
        float4 acc = make_float4(sh_b[cg * 4 + 0], sh_b[cg * 4 + 1],
                                 sh_b[cg * 4 + 2], sh_b[cg * 4 + 3]);
#pragma unroll
        for (int ci = 0; ci < CIN; ci++) {
#pragma unroll
            for (int k = 0; k < 3; k++) {
                float xv = sh_in[ci * (TILE + 2 * DIL) + p + k * DIL];
                const float4 wv = *(const float4*)&sh_w[(ci * 3 + k) * 16 + cg * 4];
                acc.x += xv * wv.x; acc.y += xv * wv.y;
                acc.z += xv * wv.z; acc.w += xv * wv.w;
            }
        }
        int t = t0 + p;
        outb[(size_t)(cg * 4 + 0) * TT + t] = fmaxf(acc.x, 0.f);
        outb[(size_t)(cg * 4 + 1) * TT + t] = fmaxf(acc.y, 0.f);
        outb[(size_t)(cg * 4 + 2) * TT + t] = fmaxf(acc.z, 0.f);
        outb[(size_t)(cg * 4 + 3) * TT + t] = fmaxf(acc.w, 0.f);
    }
}

// ---------------- kernel 3: eeg row norms ----------------
__global__ void k_eegnorm()
{
    __shared__ float red[256];
    int r = blockIdx.x;                       // [0, 1024): b*16 + j
    int tid = threadIdx.x;
    const float* p = g_x3 + (size_t)r * TT;
    float ss = 0.f;
    for (int t = tid; t < L3_LEN; t += 256) { float v = p[t]; ss += v * v; }
    red[tid] = ss; __syncthreads();
    for (int st = 128; st > 0; st >>= 1) {
        if (tid < st) red[tid] += red[tid + st];
        __syncthreads();
    }
    if (tid == 0) g_nx[r] = fmaxf(sqrtf(red[0]), 1e-8f);
}

// ---------------- kernel 4: zero accumulators ----------------
__global__ void k_zero()
{
    int i = blockIdx.x * 256 + threadIdx.x;
    if (i < BB * SS * 256) g_dot[i] = 0.f;
    if (i < BB * SS * 16)  g_nst2[i] = 0.f;
}

// ---------------- kernel 5: fused stimulus stack + dot + sumsq ----------------
// grid: (tiles=64, n=512) ; n = s*B + b ; block 256
__global__ void k_stim(const float* __restrict__ stim,
                       const float* __restrict__ ws1, const float* __restrict__ bs1,
                       const float* __restrict__ ws2, const float* __restrict__ bs2,
                       const float* __restrict__ ws3, const float* __restrict__ bs3)
{
    const int TILE = 128;
    __shared__ float sh_in[TILE + 26];
    __shared__ float sh_l1[16 * (TILE + 24)];
    __shared__ float sh_l2[16 * (TILE + 18)];
    __shared__ __align__(16) float sh_l3[16 * 132];
    __shared__ __align__(16) float sh_x [16 * 132];
    __shared__ __align__(16) float sh_w1[48];
    __shared__ __align__(16) float sh_w2[768];
    __shared__ __align__(16) float sh_w3[768];
    __shared__ float sh_b1[16], sh_b2[16], sh_b3[16];
    __shared__ float sh_ss[16];

    int n  = blockIdx.y;
    int s  = n >> 6;          // n = s*B + b, B=64
    int b  = n & 63;
    int t0 = blockIdx.x * TILE;
    int tid = threadIdx.x;
    int nOut = min(TILE, L3_LEN - t0);
    int n1 = nOut + 24, n2 = nOut + 18, nIn = nOut + 26;

    if (tid < 48) { int co = tid & 15, k = tid >> 4; sh_w1[k * 16 + co] = ws1[co * 3 + k]; }
    for (int i = tid; i < 768; i += 256) {
        int co = i & 15; int rem = i >> 4; int k = rem % 3; int ci = rem / 3;
        sh_w2[i] = ws2[(co * 16 + ci) * 3 + k];
        sh_w3[i] = ws3[(co * 16 + ci) * 3 + k];
    }
    if (tid < 16) { sh_b1[tid] = bs1[tid]; sh_b2[tid] = bs2[tid]; sh_b3[tid] = bs3[tid]; sh_ss[tid] = 0.f; }

    // raw stimulus sequence: stimulus[b][s][t][0]
    const float* inb = stim + ((size_t)(b * SS + s)) * TT + t0;
    if (tid < nIn) sh_in[tid] = inb[tid];

    // eeg feature tile
    {
        const float* xb = g_x3 + ((size_t)b * 16) * TT + t0;
#pragma unroll
        for (int j = 0; j < 16; j++)
            if (tid < nOut) sh_x[j * 132 + tid] = xb[(size_t)j * TT + tid];
    }
    __syncthreads();

    // layer 1: 1 -> 16, dil 1
    for (int it = tid; it < 16 * n1; it += 256) {
        int c = it & 15, q = it >> 4;
        float acc = sh_b1[c];
        acc += sh_in[q + 0] * sh_w1[ 0 + c];
        acc += sh_in[q + 1] * sh_w1[16 + c];
        acc += sh_in[q + 2] * sh_w1[32 + c];
        sh_l1[c * (TILE + 24) + q] = fmaxf(acc, 0.f);
    }
    __syncthreads();

    // layer 2: 16 -> 16, dil 3
    for (int it = tid; it < 4 * n2; it += 256) {
        int cg = it & 3, p = it >> 2;
        float4 acc = make_float4(sh_b2[cg * 4 + 0], sh_b2[cg * 4 + 1],
                                 sh_b2[cg * 4 + 2], sh_b2[cg * 4 + 3]);
#pragma unroll
        for (int ci = 0; ci < 16; ci++) {
#pragma unroll
            for (int k = 0; k < 3; k++) {
                float xv = sh_l1[ci * (TILE + 24) + p + k * 3];
                const float4 wv = *(const float4*)&sh_w2[(ci * 3 + k) * 16 + cg * 4];
                acc.x += xv * wv.x; acc.y += xv * wv.y;
                acc.z += xv * wv.z; acc.w += xv * wv.w;
            }
        }
        sh_l2[(cg * 4 + 0) * (TILE + 18) + p] = fmaxf(acc.x, 0.f);
        sh_l2[(cg * 4 + 1) * (TILE + 18) + p] = fmaxf(acc.y, 0.f);
        sh_l2[(cg * 4 + 2) * (TILE + 18) + p] = fmaxf(acc.z, 0.f);
        sh_l2[(cg * 4 + 3) * (TILE + 18) + p] = fmaxf(acc.w, 0.f);
    }
    __syncthreads();

    // layer 3: 16 -> 16, dil 9
    for (int it = tid; it < 4 * nOut; it += 256) {
        int cg = it & 3, p = it >> 2;
        float4 acc = make_float4(sh_b3[cg * 4 + 0], sh_b3[cg * 4 + 1],
                                 sh_b3[cg * 4 + 2], sh_b3[cg * 4 + 3]);
#pragma unroll
        for (int ci = 0; ci < 16; ci++) {
#pragma unroll
            for (int k = 0; k < 3; k++) {
                float xv = sh_l2[ci * (TILE + 18) + p + k * 9];
                const float4 wv = *(const float4*)&sh_w3[(ci * 3 + k) * 16 + cg * 4];
                acc.x += xv * wv.x; acc.y += xv * wv.y;
                acc.z += xv * wv.z; acc.w += xv * wv.w;
            }
        }
        sh_l3[(cg * 4 + 0) * 132 + p] = fmaxf(acc.x, 0.f);
        sh_l3[(cg * 4 + 1) * 132 + p] = fmaxf(acc.y, 0.f);
        sh_l3[(cg * 4 + 2) * 132 + p] = fmaxf(acc.z, 0.f);
        sh_l3[(cg * 4 + 3) * 132 + p] = fmaxf(acc.w, 0.f);
    }
    __syncthreads();

    // dot: thread (i,j) accumulates over the tile
    int i = tid >> 4, j = tid & 15;
    float acc = 0.f;
    int t4 = nOut & ~3;
    const float4* a4 = (const float4*)(sh_l3 + i * 132);
    const float4* c4 = (const float4*)(sh_x  + j * 132);
    for (int t = 0; t < (t4 >> 2); t++) {
        float4 av = a4[t], bv = c4[t];
        acc += av.x * bv.x + av.y * bv.y + av.z * bv.z + av.w * bv.w;
    }
    for (int t = t4; t < nOut; t++) acc += sh_l3[i * 132 + t] * sh_x[j * 132 + t];
    atomicAdd(&g_dot[(size_t)n * 256 + tid], acc);

    // sumsq of stim features (each thread covers t in [j*8, j*8+8))
    float ssq = 0.f;
    int te = min((j + 1) * 8, nOut);
    for (int t = j * 8; t < te; t++) { float v = sh_l3[i * 132 + t]; ssq += v * v; }
    atomicAdd(&sh_ss[i], ssq);
    __syncthreads();
    if (tid < 16) atomicAdd(&g_nst2[n * 16 + tid], sh_ss[tid]);
}

// ---------------- kernel 6: finalize cosine + linear ----------------
__global__ void k_final(const float* __restrict__ w_lin,
                        const float* __restrict__ b_lin,
                        float* __restrict__ out)
{
    __shared__ float red[256];
    int n = blockIdx.x;          // n = s*B + b
    int s = n >> 6;
    int b = n & 63;
    int tid = threadIdx.x;
    int i = tid >> 4, j = tid & 15;

    float ni = fmaxf(sqrtf(g_nst2[n * 16 + i]), 1e-8f);
    float nj = g_nx[b * 16 + j];
    float v  = w_lin[tid] * g_dot[(size_t)n * 256 + tid] / (ni * nj);

    red[tid] = v; __syncthreads();
    for (int st = 128; st > 0; st >>= 1) {
        if (tid < st) red[tid] += red[tid + st];
        __syncthreads();
    }
    if (tid == 0) out[b * SS + s] = red[0] + b_lin[0];
}

// ---------------- launch ----------------
extern "C" void kernel_launch(void* const* d_in, const int* in_sizes, int n_in,
                              void* d_out, int out_size)
{
    const float* eeg   = (const float*)d_in[0];
    const float* stim  = (const float*)d_in[1];
    const float* w_eeg = (const float*)d_in[2];
    const float* b_eeg = (const float*)d_in[3];
    const float* w_e1  = (const float*)d_in[4];
    const float* b_e1  = (const float*)d_in[5];
    const float* w_e2  = (const float*)d_in[6];
    const float* b_e2  = (const float*)d_in[7];
    const float* w_e3  = (const float*)d_in[8];
    const float* b_e3  = (const float*)d_in[9];
    const float* w_s1  = (const float*)d_in[10];
    const float* b_s1  = (const float*)d_in[11];
    const float* w_s2  = (const float*)d_in[12];
    const float* b_s2  = (const float*)d_in[13];
    const float* w_s3  = (const float*)d_in[14];
    const float* b_s3  = (const float*)d_in[15];
    const float* w_lin = (const float*)d_in[16];
    const float* b_lin = (const float*)d_in[17];
    float* out = (float*)d_out;

    // eeg path
    k_head<<<(BB * TT) / 256, 256>>>(eeg, w_eeg, b_eeg);
    k_conv<8, 1><<<dim3(32, BB), 256>>>(0, 1, w_e1, b_e1, TT,     L1_LEN);
    k_conv<16, 3><<<dim3(32, BB), 256>>>(1, 2, w_e2, b_e2, L1_LEN, L2_LEN);
    k_conv<16, 9><<<dim3(32, BB), 256>>>(2, 3, w_e3, b_e3, L2_LEN, L3_LEN);
    k_eegnorm<<<BB * 16, 256>>>();

    // accumulators
    k_zero<<<(BB * SS * 256) / 256, 256>>>();

    // stimulus path (fused) — accumulates dot + sumsq
    k_stim<<<dim3(64, BB * SS), 256>>>(stim, w_s1, b_s1, w_s2, b_s2, w_s3, b_s3);

    // finalize
    k_final<<<BB * SS, 256>>>(w_lin, b_lin, out);
}

// round 3
// speedup vs baseline: 1.4604x; 1.4604x over previous
#include <cuda_runtime.h>
#include <cuda_bf16.h>
#include <math.h>

typedef unsigned long long ull;

// ---------------- problem constants ----------------
#define BB 64
#define SS 8
#define TT 8192
#define L1_LEN 8190   // after dil-1 conv
#define L2_LEN 8184   // after dil-3 conv
#define L3_LEN 8166   // after dil-9 conv

// ---------------- packed f32x2 helpers ----------------
__device__ __forceinline__ ull pk2(float lo, float hi) {
    ull r; asm("mov.b64 %0, {%1, %2};" : "=l"(r) : "f"(lo), "f"(hi)); return r;
}
__device__ __forceinline__ void up2(ull v, float& lo, float& hi) {
    asm("mov.b64 {%0, %1}, %2;" : "=f"(lo), "=f"(hi) : "l"(v));
}
__device__ __forceinline__ void fma2(ull& d, ull a, ull b) {
    asm("fma.rn.f32x2 %0, %1, %2, %0;" : "+l"(d) : "l"(a), "l"(b));
}

// ---------------- device scratch ----------------
__device__ float g_x0[(size_t)BB * 8  * TT];
__device__ float g_x1[(size_t)BB * 16 * TT];
__device__ float g_x2[(size_t)BB * 16 * TT];
__device__ float g_x3[(size_t)BB * 16 * TT];
__device__ float g_nx[BB * 16];
__device__ float g_nst2[BB * SS * 16];
__device__ float g_dot[(size_t)BB * SS * 256];

__device__ __forceinline__ float* bufptr(int id) {
    switch (id) {
        case 0: return g_x0;
        case 1: return g_x1;
        case 2: return g_x2;
        default: return g_x3;
    }
}

// ---------------- kernel 1: eeg 1x1 head (64 -> 8) ----------------
__global__ void k_head(const float* __restrict__ eeg,
                       const float* __restrict__ w,      // [8][64]
                       const float* __restrict__ bias)   // [8]
{
    __shared__ float sh_w[512];
    __shared__ float sh_b[8];
    int tid = threadIdx.x;
    for (int i = tid; i < 512; i += 256) sh_w[i] = w[i];
    if (tid < 8) sh_b[tid] = bias[tid];
    __syncthreads();

    size_t idx = (size_t)blockIdx.x * 256 + tid;
    int b = (int)(idx >> 13);
    int t = (int)(idx & (TT - 1));

    const float4* ep = (const float4*)(eeg + idx * 64);
    float acc[8];
#pragma unroll
    for (int c = 0; c < 8; c++) acc[c] = sh_b[c];
#pragma unroll
    for (int q = 0; q < 16; q++) {
        float4 v = ep[q];
#pragma unroll
        for (int c = 0; c < 8; c++) {
            acc[c] += v.x * sh_w[c * 64 + q * 4 + 0]
                    + v.y * sh_w[c * 64 + q * 4 + 1]
                    + v.z * sh_w[c * 64 + q * 4 + 2]
                    + v.w * sh_w[c * 64 + q * 4 + 3];
        }
    }
    float* ob = g_x0 + ((size_t)b * 8) * TT + t;
#pragma unroll
    for (int c = 0; c < 8; c++) ob[(size_t)c * TT] = acc[c];
}

// ---------------- kernel 2: packed dilated conv+relu (eeg path) ----------------
template <int CIN, int DIL>
__global__ void __launch_bounds__(256)
k_conv2(int inId, int outId,
        const float* __restrict__ w,     // [16][CIN][3]
        const float* __restrict__ bias,  // [16]
        int Lin, int Lout)
{
    const int PIN = (256 + 2 * DIL + 5) & ~3;
    __shared__ __align__(16) float sh_in[CIN * PIN];
    __shared__ __align__(16) float sh_w[CIN * 48];
    __shared__ ull sh_bp[8];

    const float* in  = bufptr(inId);
    float*       out = bufptr(outId);

    int b   = blockIdx.y;
    int t0  = blockIdx.x * 256;
    int tid = threadIdx.x;
    int tileOut = min(256, Lout - t0);
    if (tileOut <= 0) return;
    int nIn = tileOut + 2 * DIL;

    for (int i = tid; i < CIN * 48; i += 256) {
        int co = i & 15; int rem = i >> 4; int k = rem % 3; int ci = rem / 3;
        sh_w[i] = w[(co * CIN + ci) * 3 + k];
    }
    if (tid < 8) sh_bp[tid] = pk2(bias[2 * tid], bias[2 * tid + 1]);

    const float* inb = in + ((size_t)b * CIN) * TT;
    for (int i = tid; i < CIN * nIn; i += 256) {
        int ci = i / nIn; int q = i - ci * nIn;
        int t = t0 + q;
        sh_in[ci * PIN + q] = (t < Lin) ? inb[(size_t)ci * TT + t] : 0.f;
    }
    __syncthreads();

    float* ob = out + ((size_t)b * 16) * TT + t0;
    int items = 4 * ((tileOut + 3) >> 2);
    for (int it = tid; it < items; it += 256) {
        int cg = it & 3;
        int p  = (it >> 2) * 4;
        ull b01 = sh_bp[cg * 2], b23 = sh_bp[cg * 2 + 1];
        ull a0[4], a1[4];
#pragma unroll
        for (int t = 0; t < 4; t++) { a0[t] = b01; a1[t] = b23; }
#pragma unroll
        for (int ci = 0; ci < CIN; ci++) {
#pragma unroll
            for (int k = 0; k < 3; k++) {
                const ull* wp = (const ull*)&sh_w[(ci * 3 + k) * 16 + cg * 4];
                ull w01 = wp[0], w23 = wp[1];
                const float* xr = &sh_in[ci * PIN + p + k * DIL];
#pragma unroll
                for (int t = 0; t < 4; t++) {
                    ull x2 = pk2(xr[t], xr[t]);
                    fma2(a0[t], w01, x2);
                    fma2(a1[t], w23, x2);
                }
            }
        }
        float lo[4], hi[4], lo2[4], hi2[4];
#pragma unroll
        for (int t = 0; t < 4; t++) {
            up2(a0[t], lo[t], hi[t]);
            up2(a1[t], lo2[t], hi2[t]);
        }
        int c0 = cg * 4;
        if (p + 3 < tileOut) {
            *(float4*)&ob[(size_t)(c0 + 0) * TT + p] =
                make_float4(fmaxf(lo[0],0.f), fmaxf(lo[1],0.f), fmaxf(lo[2],0.f), fmaxf(lo[3],0.f));
            *(float4*)&ob[(size_t)(c0 + 1) * TT + p] =
                make_float4(fmaxf(hi[0],0.f), fmaxf(hi[1],0.f), fmaxf(hi[2],0.f), fmaxf(hi[3],0.f));
            *(float4*)&ob[(size_t)(c0 + 2) * TT + p] =
                make_float4(fmaxf(lo2[0],0.f), fmaxf(lo2[1],0.f), fmaxf(lo2[2],0.f), fmaxf(lo2[3],0.f));
            *(float4*)&ob[(size_t)(c0 + 3) * TT + p] =
                make_float4(fmaxf(hi2[0],0.f), fmaxf(hi2[1],0.f), fmaxf(hi2[2],0.f), fmaxf(hi2[3],0.f));
        } else {
            for (int t = 0; t < 4; t++) {
                if (p + t < tileOut) {
                    ob[(size_t)(c0 + 0) * TT + p + t] = fmaxf(lo[t],  0.f);
                    ob[(size_t)(c0 + 1) * TT + p + t] = fmaxf(hi[t],  0.f);
                    ob[(size_t)(c0 + 2) * TT + p + t] = fmaxf(lo2[t], 0.f);
                    ob[(size_t)(c0 + 3) * TT + p + t] = fmaxf(hi2[t], 0.f);
                }
            }
        }
    }
}

// ---------------- kernel 3: eeg row norms ----------------
__global__ void k_eegnorm()
{
    __shared__ float red[256];
    int r = blockIdx.x;
    int tid = threadIdx.x;
    const float* p = g_x3 + (size_t)r * TT;
    float ss = 0.f;
    for (int t = tid; t < L3_LEN; t += 256) { float v = p[t]; ss += v * v; }
    red[tid] = ss; __syncthreads();
    for (int st = 128; st > 0; st >>= 1) {
        if (tid < st) red[tid] += red[tid + st];
        __syncthreads();
    }
    if (tid == 0) g_nx[r] = fmaxf(sqrtf(red[0]), 1e-8f);
}

// ---------------- kernel 4: zero accumulators ----------------
__global__ void k_zero()
{
    int i = blockIdx.x * 256 + threadIdx.x;
    if (i < BB * SS * 256) g_dot[i] = 0.f;
    if (i < BB * SS * 16)  g_nst2[i] = 0.f;
}

// ---------------- kernel 5: fused stimulus stack + dot + sumsq ----------------
// grid (32 tiles, 512 n); block 256; TILE=256
#define P1 284   // l1 pitch (bufA), needs >= 282
#define P2 280   // l2 pitch (bufB), needs >= 277
#define P3 260   // l3 / x pitch
__global__ void __launch_bounds__(256)
k_stim(const float* __restrict__ stim,
       const float* __restrict__ ws1, const float* __restrict__ bs1,
       const float* __restrict__ ws2, const float* __restrict__ bs2,
       const float* __restrict__ ws3, const float* __restrict__ bs3)
{
    __shared__ __align__(16) float bufA[16 * P1];   // l1, then l3, then partials
    __shared__ __align__(16) float bufB[16 * P2];   // l2, then eeg x
    __shared__ __align__(16) float sh_in[P1];
    __shared__ __align__(16) float sh_w2[768];
    __shared__ __align__(16) float sh_w3[768];
    __shared__ float sh_w1[48];
    __shared__ ull sh_bp2[8], sh_bp3[8];
    __shared__ float sh_b1[16];

    int n  = blockIdx.y;          // n = s*B + b
    int s  = n >> 6;
    int b  = n & 63;
    int t0 = blockIdx.x * 256;
    int tid = threadIdx.x;
    int nOut = min(256, L3_LEN - t0);      // always even
    int n1 = nOut + 24, n2 = nOut + 18, nIn = nOut + 26;

    if (tid < 48) { int co = tid & 15, k = tid >> 4; sh_w1[k * 16 + co] = ws1[co * 3 + k]; }
    for (int i = tid; i < 768; i += 256) {
        int co = i & 15; int rem = i >> 4; int k = rem % 3; int ci = rem / 3;
        sh_w2[i] = ws2[(co * 16 + ci) * 3 + k];
        sh_w3[i] = ws3[(co * 16 + ci) * 3 + k];
    }
    if (tid < 8) {
        sh_bp2[tid] = pk2(bs2[2 * tid], bs2[2 * tid + 1]);
        sh_bp3[tid] = pk2(bs3[2 * tid], bs3[2 * tid + 1]);
    }
    if (tid < 16) sh_b1[tid] = bs1[tid];

    // FIX (R2 bug): nIn can be up to 282 > blockDim; must grid-stride this load.
    const float* inb = stim + ((size_t)(b * SS + s)) * TT + t0;
    for (int i = tid; i < nIn; i += 256) sh_in[i] = inb[i];
    __syncthreads();

    // ---- layer 1: 1 -> 16, dil 1 (scalar, cheap) ----
    for (int it = tid; it < 16 * n1; it += 256) {
        int c = it & 15, q = it >> 4;
        float acc = sh_b1[c];
        acc += sh_in[q + 0] * sh_w1[ 0 + c];
        acc += sh_in[q + 1] * sh_w1[16 + c];
        acc += sh_in[q + 2] * sh_w1[32 + c];
        bufA[c * P1 + q] = fmaxf(acc, 0.f);
    }
    __syncthreads();

    // ---- layer 2: 16 -> 16, dil 3 (packed) ----
    {
        int items = 4 * ((n2 + 3) >> 2);
        for (int it = tid; it < items; it += 256) {
            int cg = it & 3;
            int p  = (it >> 2) * 4;
            ull b01 = sh_bp2[cg * 2], b23 = sh_bp2[cg * 2 + 1];
            ull a0[4], a1[4];
#pragma unroll
            for (int t = 0; t < 4; t++) { a0[t] = b01; a1[t] = b23; }
#pragma unroll
            for (int ci = 0; ci < 16; ci++) {
#pragma unroll
                for (int k = 0; k < 3; k++) {
                    const ull* wp = (const ull*)&sh_w2[(ci * 3 + k) * 16 + cg * 4];
                    ull w01 = wp[0], w23 = wp[1];
                    const float* xr = &bufA[ci * P1 + p + k * 3];
#pragma unroll
                    for (int t = 0; t < 4; t++) {
                        ull x2 = pk2(xr[t], xr[t]);
                        fma2(a0[t], w01, x2);
                        fma2(a1[t], w23, x2);
                    }
                }
            }
            int c0 = cg * 4;
#pragma unroll
            for (int t = 0; t < 4; t++) {
                if (p + t < n2) {
                    float l, h;
                    up2(a0[t], l, h);
                    bufB[(c0 + 0) * P2 + p + t] = fmaxf(l, 0.f);
                    bufB[(c0 + 1) * P2 + p + t] = fmaxf(h, 0.f);
                    up2(a1[t], l, h);
                    bufB[(c0 + 2) * P2 + p + t] = fmaxf(l, 0.f);
                    bufB[(c0 + 3) * P2 + p + t] = fmaxf(h, 0.f);
                }
            }
        }
    }
    __syncthreads();

    // ---- layer 3: 16 -> 16, dil 9 (packed), writes l3 into bufA ----
    {
        int items = 4 * ((nOut + 3) >> 2);
        for (int it = tid; it < items; it += 256) {
            int cg = it & 3;
            int p  = (it >> 2) * 4;
            ull b01 = sh_bp3[cg * 2], b23 = sh_bp3[cg * 2 + 1];
            ull a0[4], a1[4];
#pragma unroll
            for (int t = 0; t < 4; t++) { a0[t] = b01; a1[t] = b23; }
#pragma unroll
            for (int ci = 0; ci < 16; ci++) {
#pragma unroll
                for (int k = 0; k < 3; k++) {
                    const ull* wp = (const ull*)&sh_w3[(ci * 3 + k) * 16 + cg * 4];
                    ull w01 = wp[0], w23 = wp[1];
                    const float* xr = &bufB[ci * P2 + p + k * 9];
#pragma unroll
                    for (int t = 0; t < 4; t++) {
                        ull x2 = pk2(xr[t], xr[t]);
                        fma2(a0[t], w01, x2);
                        fma2(a1[t], w23, x2);
                    }
                }
            }
            int c0 = cg * 4;
#pragma unroll
            for (int t = 0; t < 4; t++) {
                if (p + t < nOut) {
                    float l, h;
                    up2(a0[t], l, h);
                    bufA[(c0 + 0) * P3 + p + t] = fmaxf(l, 0.f);
                    bufA[(c0 + 1) * P3 + p + t] = fmaxf(h, 0.f);
                    up2(a1[t], l, h);
                    bufA[(c0 + 2) * P3 + p + t] = fmaxf(l, 0.f);
                    bufA[(c0 + 3) * P3 + p + t] = fmaxf(h, 0.f);
                }
            }
        }
    }
    __syncthreads();

    // ---- load eeg x tile into bufB (l2 dead now) ----
    {
        const float* xb = g_x3 + ((size_t)b * 16) * TT + t0;
#pragma unroll
        for (int j = 0; j < 16; j++)
            if (tid < nOut) bufB[j * P3 + tid] = xb[(size_t)j * TT + tid];
    }
    __syncthreads();

    // ---- dot phase: 2x2 register tile, 4 t-chunks ----
    int chunk = tid >> 6;
    int q = tid & 63;
    int ip = q >> 3, jp = q & 7;
    int i0 = ip * 2, j0 = jp * 2;
    const ull* A0 = (const ull*)(bufA + (i0 + 0) * P3);
    const ull* A1 = (const ull*)(bufA + (i0 + 1) * P3);
    const ull* B0 = (const ull*)(bufB + (j0 + 0) * P3);
    const ull* B1 = (const ull*)(bufB + (j0 + 1) * P3);
    int tBeg = chunk * 64;
    int tEnd = min(tBeg + 64, nOut);
    ull c00 = 0, c01 = 0, c10 = 0, c11 = 0, ss0 = 0, ss1 = 0;
    for (int t2 = tBeg >> 1; t2 < (tEnd >> 1); t2++) {
        ull a0 = A0[t2], a1 = A1[t2], b0 = B0[t2], b1 = B1[t2];
        fma2(c00, a0, b0); fma2(c01, a0, b1);
        fma2(c10, a1, b0); fma2(c11, a1, b1);
        if (jp == 0) { fma2(ss0, a0, a0); fma2(ss1, a1, a1); }
    }
    __syncthreads();   // all l3/x reads done before bufA reuse

    {
        float l, h;
        float* part = bufA;
        up2(c00, l, h); part[chunk * 256 + (i0 + 0) * 16 + j0 + 0] = l + h;
        up2(c01, l, h); part[chunk * 256 + (i0 + 0) * 16 + j0 + 1] = l + h;
        up2(c10, l, h); part[chunk * 256 + (i0 + 1) * 16 + j0 + 0] = l + h;
        up2(c11, l, h); part[chunk * 256 + (i0 + 1) * 16 + j0 + 1] = l + h;
        if (jp == 0) {
            up2(ss0, l, h); part[1024 + chunk * 16 + i0 + 0] = l + h;
            up2(ss1, l, h); part[1024 + chunk * 16 + i0 + 1] = l + h;
        }
    }
    __syncthreads();

    float d = bufA[tid] + bufA[256 + tid] + bufA[512 + tid] + bufA[768 + tid];
    atomicAdd(&g_dot[(size_t)n * 256 + tid], d);
    if (tid < 16) {
        float sv = bufA[1024 + tid] + bufA[1024 + 16 + tid]
                 + bufA[1024 + 32 + tid] + bufA[1024 + 48 + tid];
        atomicAdd(&g_nst2[n * 16 + tid], sv);
    }
}

// ---------------- kernel 6: finalize ----------------
__global__ void k_final(const float* __restrict__ w_lin,
                        const float* __restrict__ b_lin,
                        float* __restrict__ out)
{
    __shared__ float red[256];
    int n = blockIdx.x;
    int s = n >> 6;
    int b = n & 63;
    int tid = threadIdx.x;
    int i = tid >> 4, j = tid & 15;

    float ni = fmaxf(sqrtf(g_nst2[n * 16 + i]), 1e-8f);
    float nj = g_nx[b * 16 + j];
    float v  = w_lin[tid] * g_dot[(size_t)n * 256 + tid] / (ni * nj);

    red[tid] = v; __syncthreads();
    for (int st = 128; st > 0; st >>= 1) {
        if (tid < st) red[tid] += red[tid + st];
        __syncthreads();
    }
    if (tid == 0) out[b * SS + s] = red[0] + b_lin[0];
}

// ---------------- launch ----------------
extern "C" void kernel_launch(void* const* d_in, const int* in_sizes, int n_in,
                              void* d_out, int out_size)
{
    const float* eeg   = (const float*)d_in[0];
    const float* stim  = (const float*)d_in[1];
    const float* w_eeg = (const float*)d_in[2];
    const float* b_eeg = (const float*)d_in[3];
    const float* w_e1  = (const float*)d_in[4];
    const float* b_e1  = (const float*)d_in[5];
    const float* w_e2  = (const float*)d_in[6];
    const float* b_e2  = (const float*)d_in[7];
    const float* w_e3  = (const float*)d_in[8];
    const float* b_e3  = (const float*)d_in[9];
    const float* w_s1  = (const float*)d_in[10];
    const float* b_s1  = (const float*)d_in[11];
    const float* w_s2  = (const float*)d_in[12];
    const float* b_s2  = (const float*)d_in[13];
    const float* w_s3  = (const float*)d_in[14];
    const float* b_s3  = (const float*)d_in[15];
    const float* w_lin = (const float*)d_in[16];
    const float* b_lin = (const float*)d_in[17];
    float* out = (float*)d_out;

    k_head<<<(BB * TT) / 256, 256>>>(eeg, w_eeg, b_eeg);
    k_conv2<8, 1><<<dim3(32, BB), 256>>>(0, 1, w_e1, b_e1, TT,     L1_LEN);
    k_conv2<16, 3><<<dim3(32, BB), 256>>>(1, 2, w_e2, b_e2, L1_LEN, L2_LEN);
    k_conv2<16, 9><<<dim3(32, BB), 256>>>(2, 3, w_e3, b_e3, L2_LEN, L3_LEN);
    k_eegnorm<<<BB * 16, 256>>>();

    k_zero<<<(BB * SS * 256) / 256, 256>>>();

    k_stim<<<dim3(32, BB * SS), 256>>>(stim, w_s1, b_s1, w_s2, b_s2, w_s3, b_s3);

    k_final<<<BB * SS, 256>>>(w_lin, b_lin, out);
}